// round 9
// baseline (speedup 1.0000x reference)
#include <cuda_runtime.h>
#include <cuda_fp16.h>
#include <math.h>

#define NMAX 100000
#define EMAX 1600000
#define CSRMAX (EMAX + 16 * NMAX)
#define EPS 1e-5f
#define SCAN_BLK 1024
#define MAX_BLKS 128                 // ceil(100000/1024)=98 <= 128

// ---- device scratch (no allocations allowed). All zero at module load. ----
__device__ int      g_deg [NMAX];        // re-zeroed at end of each launch
__device__ int      g_off [NMAX + 1];
__device__ int      g_cur [NMAX];
__device__ unsigned g_state[MAX_BLKS];   // re-zeroed at end of each launch
__device__ float    g_dinv[NMAX];
__device__ int      g_csr [CSRMAX];      // real slots by k_build, padding by k_pad
__device__ __half   g_hA  [(size_t)(NMAX + 1) * 64];  // ping  (row NMAX never written => 0)
__device__ __half   g_hB  [(size_t)(NMAX + 1) * 64];  // pong  (row NMAX never written => 0)

// ---------- degree count ----------
__global__ void k_count(const int* __restrict__ row, int E) {
    int t = blockIdx.x * blockDim.x + threadIdx.x;
    int stride = gridDim.x * blockDim.x;
    #pragma unroll
    for (int j = 0; j < 4; j++) {
        int e = t + j * stride;
        if (e < E) atomicAdd(&g_deg[row[e]], 1);
    }
}

// ---------- decoupled-lookback scan (warp-parallel lookback) + dinv ----------
__global__ __launch_bounds__(SCAN_BLK)
void k_scan_lb(int N) {
    __shared__ int warp_sums[32];
    __shared__ int s_prefix;

    int bid  = blockIdx.x;
    int tid  = threadIdx.x;
    int lane = tid & 31;
    int wid  = tid >> 5;
    int i    = bid * SCAN_BLK + tid;

    int v = (i < N) ? g_deg[i] : 0;
    if (i < N) g_dinv[i] = rsqrtf((float)v + 1.0f);   // +1 = self loop
    int vp = (v + 15) & ~15;                          // padded degree

    int x = vp;
    #pragma unroll
    for (int d = 1; d < 32; d <<= 1) {
        int t = __shfl_up_sync(0xFFFFFFFFu, x, d);
        if (lane >= d) x += t;
    }
    if (lane == 31) warp_sums[wid] = x;
    __syncthreads();
    if (wid == 0) {
        int y = warp_sums[lane];
        #pragma unroll
        for (int d = 1; d < 32; d <<= 1) {
            int t = __shfl_up_sync(0xFFFFFFFFu, y, d);
            if (lane >= d) y += t;
        }
        warp_sums[lane] = y;
    }
    __syncthreads();

    int block_incl  = x + (wid > 0 ? warp_sums[wid - 1] : 0);
    int block_total = warp_sums[31];

    if (wid == 0) {
        if (bid == 0) {
            if (lane == 0) {
                s_prefix = 0;
                atomicExch(&g_state[0], (2u << 28) | (unsigned)block_total);
            }
        } else {
            if (lane == 0)
                atomicExch(&g_state[bid], (1u << 28) | (unsigned)block_total);
            int run = 0;
            int j0 = bid - 1;
            while (true) {
                int idx = j0 - lane;
                unsigned st = (idx >= 0) ? atomicAdd(&g_state[idx], 0u) : (2u << 28);
                if (__any_sync(0xFFFFFFFFu, (st >> 28) == 0u)) { __nanosleep(20); continue; }
                unsigned pm = __ballot_sync(0xFFFFFFFFu, (st >> 28) == 2u);
                if (pm) {
                    int L = __ffs((int)pm) - 1;
                    int val = (lane <= L) ? (int)(st & 0x0FFFFFFFu) : 0;
                    run += __reduce_add_sync(0xFFFFFFFFu, val);
                    break;
                } else {
                    run += __reduce_add_sync(0xFFFFFFFFu, (int)(st & 0x0FFFFFFFu));
                    j0 -= 32;
                }
            }
            if (lane == 0) {
                s_prefix = run;
                atomicExch(&g_state[bid], (2u << 28) | (unsigned)(run + block_total));
            }
        }
    }
    __syncthreads();

    if (tid == 0 && bid == (int)gridDim.x - 1)
        g_off[N] = s_prefix + block_total;

    int ex = s_prefix + block_incl - vp;              // exclusive prefix (16-aligned)
    if (i < N) { g_off[i] = ex; g_cur[i] = ex; }
}

// ---------- pad: fill ONLY padding slots with dummy index (disjoint from build) ----------
__global__ void k_pad(int N) {
    int i = blockIdx.x * blockDim.x + threadIdx.x;
    if (i >= N) return;
    int d = g_deg[i];
    int p = g_off[i] + d;
    int e = g_off[i] + ((d + 15) & ~15);
    for (; p < e; p++) g_csr[p] = NMAX;
}

// ---------- zero deg/state for the NEXT launch (after scan consumed them) ----------
__global__ void k_zero_next(int N) {
    int i = blockIdx.x * blockDim.x + threadIdx.x;
    if (i < N) g_deg[i] = 0;
    if (i < MAX_BLKS) g_state[i] = 0;
}

// ---------- scatter real edges ----------
__global__ void k_build(const int* __restrict__ row, const int* __restrict__ col, int E) {
    int t = blockIdx.x * blockDim.x + threadIdx.x;
    int stride = gridDim.x * blockDim.x;
    #pragma unroll
    for (int j = 0; j < 4; j++) {
        int e = t + j * stride;
        if (e < E) {
            int pos = atomicAdd(&g_cur[row[e]], 1);
            g_csr[pos] = col[e];
        }
    }
}

// ------------------- GEMM (layer 1): hs = (in @ W) * dinv[row], fp16 out ----------
#define GEMM_ROWS 64

__global__ __launch_bounds__(256)
void k_gemm(const float* __restrict__ in, const float* __restrict__ W,
            __half* __restrict__ out, int N)
{
    __shared__ float Wt[64][66];
    __shared__ float Xs[GEMM_ROWS][64];

    int tid = threadIdx.x;
    int row0 = blockIdx.x * GEMM_ROWS;

    #pragma unroll
    for (int i = tid; i < 64 * 64; i += 256) {
        int k = i >> 6, c = i & 63;
        Wt[c][k] = W[i];
    }
    #pragma unroll
    for (int i = tid; i < GEMM_ROWS * 16; i += 256) {
        int r = i >> 4, k4 = (i & 15);
        int gr = row0 + r;
        float4 v = (gr < N) ? reinterpret_cast<const float4*>(in)[(size_t)gr * 16 + k4]
                            : make_float4(0.f, 0.f, 0.f, 0.f);
        reinterpret_cast<float4*>(&Xs[r][0])[k4] = v;
    }
    __syncthreads();

    int cg = tid & 15;
    int rg = tid >> 4;
    int r0 = rg * 4;

    unsigned long long acc[4][4];
    #pragma unroll
    for (int a = 0; a < 4; a++)
        #pragma unroll
        for (int b = 0; b < 4; b++)
            acc[a][b] = 0ULL;

    #pragma unroll 8
    for (int kp = 0; kp < 32; kp++) {
        unsigned long long xv[4], wv[4];
        #pragma unroll
        for (int a = 0; a < 4; a++)
            xv[a] = *reinterpret_cast<const unsigned long long*>(&Xs[r0 + a][kp * 2]);
        #pragma unroll
        for (int b = 0; b < 4; b++)
            wv[b] = *reinterpret_cast<const unsigned long long*>(&Wt[cg + 16 * b][kp * 2]);
        #pragma unroll
        for (int a = 0; a < 4; a++)
            #pragma unroll
            for (int b = 0; b < 4; b++)
                asm("fma.rn.f32x2 %0, %1, %2, %0;"
                    : "+l"(acc[a][b]) : "l"(xv[a]), "l"(wv[b]));
    }

    #pragma unroll
    for (int a = 0; a < 4; a++) {
        int gr = row0 + r0 + a;
        if (gr < N) {
            float di = g_dinv[gr];
            #pragma unroll
            for (int b = 0; b < 4; b++) {
                float lo, hi;
                asm("mov.b64 {%0,%1}, %2;" : "=f"(lo), "=f"(hi) : "l"(acc[a][b]));
                out[(size_t)gr * 64 + cg + 16 * b] = __float2half_rn((lo + hi) * di);
            }
        }
    }
}

// ------------- FUSED: pull(h_in) + BN + ReLU -> (opt emb store) -> GEMM -> h_out -------------
// h_in and h_out MUST be different buffers (cross-block gather vs write race).
#define FUSE_ROWS 32

__global__ __launch_bounds__(512)
void k_fused(const __half* __restrict__ h_in, const float* __restrict__ bias,
             const float* __restrict__ gam, const float* __restrict__ bet,
             const float* __restrict__ mu,  const float* __restrict__ var,
             float* __restrict__ emb_out,           // nullptr = don't store pull result
             const float* __restrict__ W,
             __half* __restrict__ h_out, int N)
{
    __shared__ float Wt[64][66];
    __shared__ float Xs[FUSE_ROWS][64];

    int tid = threadIdx.x;
    int row0 = blockIdx.x * FUSE_ROWS;

    // phase 0: load W transposed
    #pragma unroll
    for (int i = tid; i < 64 * 64; i += 512) {
        int k = i >> 6, c = i & 63;
        Wt[c][k] = W[i];
    }

    // phase 1: pull + BN + ReLU for this block's 32 nodes
    {
        int g = tid >> 4, k = tid & 15;
        int i = row0 + g;
        float4 acc = make_float4(0.f, 0.f, 0.f, 0.f);

        if (i < N) {
            const uint2* h2 = reinterpret_cast<const uint2*>(h_in);
            {   // self term
                uint2 sv = __ldg(&h2[(size_t)i * 16 + k]);
                float2 f0 = __half22float2(*reinterpret_cast<__half2*>(&sv.x));
                float2 f1 = __half22float2(*reinterpret_cast<__half2*>(&sv.y));
                acc.x = f0.x; acc.y = f0.y; acc.z = f1.x; acc.w = f1.y;
            }
            int p   = g_off[i];
            int end = g_off[i + 1];
            for (; p < end; p += 16) {
                const int4* c4 = reinterpret_cast<const int4*>(&g_csr[p]);
                int4 a0 = __ldg(c4 + 0);
                int4 a1 = __ldg(c4 + 1);
                int4 a2 = __ldg(c4 + 2);
                int4 a3 = __ldg(c4 + 3);
                int cj[16] = { a0.x, a0.y, a0.z, a0.w,
                               a1.x, a1.y, a1.z, a1.w,
                               a2.x, a2.y, a2.z, a2.w,
                               a3.x, a3.y, a3.z, a3.w };
                #pragma unroll
                for (int jp = 0; jp < 8; jp++) {
                    uint2 v0 = __ldg(&h2[(size_t)cj[2 * jp]     * 16 + k]);
                    uint2 v1 = __ldg(&h2[(size_t)cj[2 * jp + 1] * 16 + k]);
                    __half2 s0 = __hadd2(*reinterpret_cast<__half2*>(&v0.x),
                                         *reinterpret_cast<__half2*>(&v1.x));
                    __half2 s1 = __hadd2(*reinterpret_cast<__half2*>(&v0.y),
                                         *reinterpret_cast<__half2*>(&v1.y));
                    float2 f0 = __half22float2(s0);
                    float2 f1 = __half22float2(s1);
                    acc.x += f0.x; acc.y += f0.y; acc.z += f1.x; acc.w += f1.y;
                }
            }

            float di = g_dinv[i];
            float4 bv = reinterpret_cast<const float4*>(bias)[k];
            acc.x = fmaf(acc.x, di, bv.x);
            acc.y = fmaf(acc.y, di, bv.y);
            acc.z = fmaf(acc.z, di, bv.z);
            acc.w = fmaf(acc.w, di, bv.w);

            int k4 = k << 2;
            #pragma unroll
            for (int j = 0; j < 4; j++) {
                float a = gam[k4 + j] * rsqrtf(var[k4 + j] + EPS);
                float c = bet[k4 + j] - mu[k4 + j] * a;
                float* f = (&acc.x) + j;
                *f = fmaxf(fmaf(*f, a, c), 0.0f);
            }
            if (emb_out)
                reinterpret_cast<float4*>(emb_out)[(size_t)i * 16 + k] = acc;
        }
        reinterpret_cast<float4*>(&Xs[g][0])[k] = acc;
    }
    __syncthreads();

    // phase 2: gemm — each thread: 1 row, 4 cols, K paired via f32x2
    {
        int cg = tid & 15;
        int r  = tid >> 4;     // 0..31

        unsigned long long acc[4] = {0ULL, 0ULL, 0ULL, 0ULL};

        #pragma unroll 8
        for (int kp = 0; kp < 32; kp++) {
            unsigned long long xv =
                *reinterpret_cast<const unsigned long long*>(&Xs[r][kp * 2]);
            #pragma unroll
            for (int b = 0; b < 4; b++) {
                unsigned long long wv =
                    *reinterpret_cast<const unsigned long long*>(&Wt[cg + 16 * b][kp * 2]);
                asm("fma.rn.f32x2 %0, %1, %2, %0;" : "+l"(acc[b]) : "l"(xv), "l"(wv));
            }
        }

        int gr = row0 + r;
        if (gr < N) {
            float di = g_dinv[gr];
            #pragma unroll
            for (int b = 0; b < 4; b++) {
                float lo, hi;
                asm("mov.b64 {%0,%1}, %2;" : "=f"(lo), "=f"(hi) : "l"(acc[b]));
                h_out[(size_t)gr * 64 + cg + 16 * b] = __float2half_rn((lo + hi) * di);
            }
        }
    }
}

// ------------------- final pull (layer 3, no BN) -------------------
__global__ __launch_bounds__(256)
void k_pull(const __half* __restrict__ h, const float* __restrict__ bias,
            float* __restrict__ out, int N)
{
    int idx = blockIdx.x * blockDim.x + threadIdx.x;
    if (idx >= N * 16) return;
    int i = idx >> 4, k = idx & 15;

    const uint2* h2 = reinterpret_cast<const uint2*>(h);

    float4 acc;
    {
        uint2 sv = __ldg(&h2[(size_t)i * 16 + k]);
        float2 f0 = __half22float2(*reinterpret_cast<__half2*>(&sv.x));
        float2 f1 = __half22float2(*reinterpret_cast<__half2*>(&sv.y));
        acc.x = f0.x; acc.y = f0.y; acc.z = f1.x; acc.w = f1.y;
    }

    int p   = g_off[i];
    int end = g_off[i + 1];
    for (; p < end; p += 16) {
        const int4* c4 = reinterpret_cast<const int4*>(&g_csr[p]);
        int4 a0 = __ldg(c4 + 0);
        int4 a1 = __ldg(c4 + 1);
        int4 a2 = __ldg(c4 + 2);
        int4 a3 = __ldg(c4 + 3);
        int cj[16] = { a0.x, a0.y, a0.z, a0.w,
                       a1.x, a1.y, a1.z, a1.w,
                       a2.x, a2.y, a2.z, a2.w,
                       a3.x, a3.y, a3.z, a3.w };
        #pragma unroll
        for (int jp = 0; jp < 8; jp++) {
            uint2 v0 = __ldg(&h2[(size_t)cj[2 * jp]     * 16 + k]);
            uint2 v1 = __ldg(&h2[(size_t)cj[2 * jp + 1] * 16 + k]);
            __half2 s0 = __hadd2(*reinterpret_cast<__half2*>(&v0.x),
                                 *reinterpret_cast<__half2*>(&v1.x));
            __half2 s1 = __hadd2(*reinterpret_cast<__half2*>(&v0.y),
                                 *reinterpret_cast<__half2*>(&v1.y));
            float2 f0 = __half22float2(s0);
            float2 f1 = __half22float2(s1);
            acc.x += f0.x; acc.y += f0.y; acc.z += f1.x; acc.w += f1.y;
        }
    }

    float di = g_dinv[i];
    float4 bv = reinterpret_cast<const float4*>(bias)[k];
    acc.x = fmaf(acc.x, di, bv.x);
    acc.y = fmaf(acc.y, di, bv.y);
    acc.z = fmaf(acc.z, di, bv.z);
    acc.w = fmaf(acc.w, di, bv.w);

    reinterpret_cast<float4*>(out)[(size_t)i * 16 + k] = acc;
}

// ------------------- launch (forked-graph orchestration) -------------------
extern "C" void kernel_launch(void* const* d_in, const int* in_sizes, int n_in,
                              void* d_out, int out_size)
{
    const float* x   = (const float*)d_in[0];
    const int*   ei  = (const int*)  d_in[1];
    const float* W1  = (const float*)d_in[2];
    const float* b1  = (const float*)d_in[3];
    const float* g1  = (const float*)d_in[4];
    const float* be1 = (const float*)d_in[5];
    const float* m1  = (const float*)d_in[6];
    const float* v1  = (const float*)d_in[7];
    const float* W2  = (const float*)d_in[8];
    const float* b2  = (const float*)d_in[9];
    const float* g2  = (const float*)d_in[10];
    const float* be2 = (const float*)d_in[11];
    const float* m2  = (const float*)d_in[12];
    const float* v2  = (const float*)d_in[13];
    const float* W3  = (const float*)d_in[14];
    const float* b3  = (const float*)d_in[15];

    int N = in_sizes[0] / 64;
    int E = in_sizes[1] / 2;

    const int* row = ei;
    const int* col = ei + E;

    float* out  = (float*)d_out;
    float* emb  = out;                      // global_embeddings [N,64]
    float* pred = out + (size_t)N * 64;     // hc_predictions    [N,64]

    __half *p_hA = nullptr, *p_hB = nullptr;
    cudaGetSymbolAddress((void**)&p_hA, g_hA);
    cudaGetSymbolAddress((void**)&p_hB, g_hB);

    static cudaStream_t sA = nullptr, sB = nullptr;
    static cudaEvent_t evScan = nullptr, evA = nullptr, evB = nullptr;
    if (sA == nullptr) {
        cudaStreamCreateWithFlags(&sA, cudaStreamNonBlocking);
        cudaStreamCreateWithFlags(&sB, cudaStreamNonBlocking);
        cudaEventCreateWithFlags(&evScan, cudaEventDisableTiming);
        cudaEventCreateWithFlags(&evA,    cudaEventDisableTiming);
        cudaEventCreateWithFlags(&evB,    cudaEventDisableTiming);
    }

    const int T = 256;
    int gN   = (N + T - 1) / T;
    int gE4  = (E + 4 * T - 1) / (4 * T);
    int gN16 = (N * 16 + T - 1) / T;
    int gG   = (N + GEMM_ROWS - 1) / GEMM_ROWS;
    int gF   = (N + FUSE_ROWS - 1) / FUSE_ROWS;
    int nb   = (N + SCAN_BLK - 1) / SCAN_BLK;

    // main chain: count (deg pre-zeroed) -> scan -> build
    k_count  <<<gE4, T>>>(row, E);
    k_scan_lb<<<nb, SCAN_BLK>>>(N);
    cudaEventRecord(evScan, 0);
    k_build  <<<gE4, T>>>(row, col, E);

    // branch A (after scan): pad CSR padding slots (disjoint from build),
    // then zero deg/state for the NEXT launch
    cudaStreamWaitEvent(sA, evScan, 0);
    k_pad      <<<gN, T, 0, sA>>>(N);
    k_zero_next<<<gN, T, 0, sA>>>(N);
    cudaEventRecord(evA, sA);

    // branch B (after scan): layer-1 GEMM (needs only dinv), overlaps with build
    cudaStreamWaitEvent(sB, evScan, 0);
    k_gemm<<<gG, T, 0, sB>>>(x, W1, p_hA, N);
    cudaEventRecord(evB, sB);

    // join
    cudaStreamWaitEvent(0, evA, 0);
    cudaStreamWaitEvent(0, evB, 0);

    // fused1: pull1(A) + BN1 + ReLU + gemm2 -> B
    k_fused<<<gF, 512>>>(p_hA, b1, g1, be1, m1, v1, nullptr, W2, p_hB, N);

    // fused2: pull2(B) + BN2 + ReLU -> emb + gemm3 -> A
    k_fused<<<gF, 512>>>(p_hB, b2, g2, be2, m2, v2, emb, W3, p_hA, N);

    // pull3: pred from A
    k_pull<<<gN16, T>>>(p_hA, b3, pred, N);
}

// round 10
// speedup vs baseline: 1.3121x; 1.3121x over previous
#include <cuda_runtime.h>
#include <cuda_fp16.h>
#include <math.h>

#define NMAX 100000
#define EMAX 1600000
#define CSRMAX (EMAX + 16 * NMAX)
#define EPS 1e-5f
#define SCAN_BLK 1024
#define MAX_BLKS 128                 // ceil(100000/1024)=98 <= 128

// ---- device scratch (no allocations allowed). All zero at module load. ----
__device__ int      g_deg [NMAX];        // re-zeroed at end of each launch
__device__ int      g_off [NMAX + 1];
__device__ unsigned g_state[MAX_BLKS];   // re-zeroed at end of each launch
__device__ float    g_dinv[NMAX];
__device__ int      g_rank[EMAX];        // within-row rank of each edge
__device__ int      g_csr [CSRMAX];      // real slots by k_build, padding by k_pad
__device__ __half   g_h   [(size_t)(NMAX + 1) * 64];  // row NMAX never written => 0
__device__ float    g_agg [(size_t)NMAX * 64];

// ---------- count + rank: one atomic pass; rank[e] = old degree ----------
__global__ void k_count(const int* __restrict__ row, int E) {
    int t = blockIdx.x * blockDim.x + threadIdx.x;
    int stride = gridDim.x * blockDim.x;
    #pragma unroll
    for (int j = 0; j < 4; j++) {
        int e = t + j * stride;
        if (e < E) g_rank[e] = atomicAdd(&g_deg[row[e]], 1);
    }
}

// ---------- decoupled-lookback scan (warp-parallel lookback) + dinv ----------
__global__ __launch_bounds__(SCAN_BLK)
void k_scan_lb(int N) {
    __shared__ int warp_sums[32];
    __shared__ int s_prefix;

    int bid  = blockIdx.x;
    int tid  = threadIdx.x;
    int lane = tid & 31;
    int wid  = tid >> 5;
    int i    = bid * SCAN_BLK + tid;

    int v = (i < N) ? g_deg[i] : 0;
    if (i < N) g_dinv[i] = rsqrtf((float)v + 1.0f);   // +1 = self loop
    int vp = (v + 15) & ~15;                          // padded degree

    int x = vp;
    #pragma unroll
    for (int d = 1; d < 32; d <<= 1) {
        int t = __shfl_up_sync(0xFFFFFFFFu, x, d);
        if (lane >= d) x += t;
    }
    if (lane == 31) warp_sums[wid] = x;
    __syncthreads();
    if (wid == 0) {
        int y = warp_sums[lane];
        #pragma unroll
        for (int d = 1; d < 32; d <<= 1) {
            int t = __shfl_up_sync(0xFFFFFFFFu, y, d);
            if (lane >= d) y += t;
        }
        warp_sums[lane] = y;
    }
    __syncthreads();

    int block_incl  = x + (wid > 0 ? warp_sums[wid - 1] : 0);
    int block_total = warp_sums[31];

    if (wid == 0) {
        if (bid == 0) {
            if (lane == 0) {
                s_prefix = 0;
                atomicExch(&g_state[0], (2u << 28) | (unsigned)block_total);
            }
        } else {
            if (lane == 0)
                atomicExch(&g_state[bid], (1u << 28) | (unsigned)block_total);
            int run = 0;
            int j0 = bid - 1;
            while (true) {
                int idx = j0 - lane;
                unsigned st = (idx >= 0) ? atomicAdd(&g_state[idx], 0u) : (2u << 28);
                if (__any_sync(0xFFFFFFFFu, (st >> 28) == 0u)) { __nanosleep(20); continue; }
                unsigned pm = __ballot_sync(0xFFFFFFFFu, (st >> 28) == 2u);
                if (pm) {
                    int L = __ffs((int)pm) - 1;
                    int val = (lane <= L) ? (int)(st & 0x0FFFFFFFu) : 0;
                    run += __reduce_add_sync(0xFFFFFFFFu, val);
                    break;
                } else {
                    run += __reduce_add_sync(0xFFFFFFFFu, (int)(st & 0x0FFFFFFFu));
                    j0 -= 32;
                }
            }
            if (lane == 0) {
                s_prefix = run;
                atomicExch(&g_state[bid], (2u << 28) | (unsigned)(run + block_total));
            }
        }
    }
    __syncthreads();

    if (tid == 0 && bid == (int)gridDim.x - 1)
        g_off[N] = s_prefix + block_total;

    int ex = s_prefix + block_incl - vp;              // exclusive prefix (16-aligned)
    if (i < N) g_off[i] = ex;
}

// ---------- pad: fill ONLY padding slots with dummy index (disjoint from build) ----------
__global__ void k_pad(int N) {
    int i = blockIdx.x * blockDim.x + threadIdx.x;
    if (i >= N) return;
    int d = g_deg[i];
    int p = g_off[i] + d;
    int e = g_off[i] + ((d + 15) & ~15);
    for (; p < e; p++) g_csr[p] = NMAX;
}

// ---------- zero deg/state for the NEXT launch (after scan+pad consumed them) ----------
__global__ void k_zero_next(int N) {
    int i = blockIdx.x * blockDim.x + threadIdx.x;
    if (i < N) g_deg[i] = 0;
    if (i < MAX_BLKS) g_state[i] = 0;
}

// ---------- scatter real edges: NO atomics (rank precomputed) ----------
__global__ void k_build(const int* __restrict__ row, const int* __restrict__ col, int E) {
    int t = blockIdx.x * blockDim.x + threadIdx.x;
    int stride = gridDim.x * blockDim.x;
    #pragma unroll
    for (int j = 0; j < 4; j++) {
        int e = t + j * stride;
        if (e < E) {
            int pos = g_off[row[e]] + g_rank[e];
            g_csr[pos] = col[e];
        }
    }
}

// ------------------- GEMM: hs = (in @ W) * dinv[row], fp16 out -------------------
#define GEMM_ROWS 64

__global__ __launch_bounds__(256)
void k_gemm(const float* __restrict__ in, const float* __restrict__ W,
            __half* __restrict__ out, int N)
{
    __shared__ float Wt[64][66];
    __shared__ float Xs[GEMM_ROWS][64];

    int tid = threadIdx.x;
    int row0 = blockIdx.x * GEMM_ROWS;

    #pragma unroll
    for (int i = tid; i < 64 * 64; i += 256) {
        int k = i >> 6, c = i & 63;
        Wt[c][k] = W[i];
    }
    #pragma unroll
    for (int i = tid; i < GEMM_ROWS * 16; i += 256) {
        int r = i >> 4, k4 = (i & 15);
        int gr = row0 + r;
        float4 v = (gr < N) ? reinterpret_cast<const float4*>(in)[(size_t)gr * 16 + k4]
                            : make_float4(0.f, 0.f, 0.f, 0.f);
        reinterpret_cast<float4*>(&Xs[r][0])[k4] = v;
    }
    __syncthreads();

    int cg = tid & 15;
    int rg = tid >> 4;
    int r0 = rg * 4;

    unsigned long long acc[4][4];
    #pragma unroll
    for (int a = 0; a < 4; a++)
        #pragma unroll
        for (int b = 0; b < 4; b++)
            acc[a][b] = 0ULL;

    #pragma unroll 8
    for (int kp = 0; kp < 32; kp++) {
        unsigned long long xv[4], wv[4];
        #pragma unroll
        for (int a = 0; a < 4; a++)
            xv[a] = *reinterpret_cast<const unsigned long long*>(&Xs[r0 + a][kp * 2]);
        #pragma unroll
        for (int b = 0; b < 4; b++)
            wv[b] = *reinterpret_cast<const unsigned long long*>(&Wt[cg + 16 * b][kp * 2]);
        #pragma unroll
        for (int a = 0; a < 4; a++)
            #pragma unroll
            for (int b = 0; b < 4; b++)
                asm("fma.rn.f32x2 %0, %1, %2, %0;"
                    : "+l"(acc[a][b]) : "l"(xv[a]), "l"(wv[b]));
    }

    #pragma unroll
    for (int a = 0; a < 4; a++) {
        int gr = row0 + r0 + a;
        if (gr < N) {
            float di = g_dinv[gr];
            #pragma unroll
            for (int b = 0; b < 4; b++) {
                float lo, hi;
                asm("mov.b64 {%0,%1}, %2;" : "=f"(lo), "=f"(hi) : "l"(acc[a][b]));
                out[(size_t)gr * 64 + cg + 16 * b] = __float2half_rn((lo + hi) * di);
            }
        }
    }
}

// ------------------- pull aggregation (fp16 gathers, fp32 accumulate) ----------
__global__ __launch_bounds__(256)
void k_pull(const __half* __restrict__ h, const float* __restrict__ bias,
            float* __restrict__ out, int N,
            const float* __restrict__ gam, const float* __restrict__ bet,
            const float* __restrict__ mu,  const float* __restrict__ var,
            int use_bn)
{
    int idx = blockIdx.x * blockDim.x + threadIdx.x;
    if (idx >= N * 16) return;
    int i = idx >> 4, k = idx & 15;

    const uint2* h2 = reinterpret_cast<const uint2*>(h);

    float4 acc;
    {   // self term
        uint2 sv = __ldg(&h2[(size_t)i * 16 + k]);
        float2 f0 = __half22float2(*reinterpret_cast<__half2*>(&sv.x));
        float2 f1 = __half22float2(*reinterpret_cast<__half2*>(&sv.y));
        acc.x = f0.x; acc.y = f0.y; acc.z = f1.x; acc.w = f1.y;
    }

    int p   = g_off[i];
    int end = g_off[i + 1];

    for (; p < end; p += 16) {
        const int4* c4 = reinterpret_cast<const int4*>(&g_csr[p]);   // 16B aligned
        int4 a0 = __ldg(c4 + 0);
        int4 a1 = __ldg(c4 + 1);
        int4 a2 = __ldg(c4 + 2);
        int4 a3 = __ldg(c4 + 3);
        int cj[16] = { a0.x, a0.y, a0.z, a0.w,
                       a1.x, a1.y, a1.z, a1.w,
                       a2.x, a2.y, a2.z, a2.w,
                       a3.x, a3.y, a3.z, a3.w };

        #pragma unroll
        for (int jp = 0; jp < 8; jp++) {
            uint2 v0 = __ldg(&h2[(size_t)cj[2 * jp]     * 16 + k]);
            uint2 v1 = __ldg(&h2[(size_t)cj[2 * jp + 1] * 16 + k]);
            __half2 s0 = __hadd2(*reinterpret_cast<__half2*>(&v0.x),
                                 *reinterpret_cast<__half2*>(&v1.x));
            __half2 s1 = __hadd2(*reinterpret_cast<__half2*>(&v0.y),
                                 *reinterpret_cast<__half2*>(&v1.y));
            float2 f0 = __half22float2(s0);
            float2 f1 = __half22float2(s1);
            acc.x += f0.x; acc.y += f0.y; acc.z += f1.x; acc.w += f1.y;
        }
    }

    float di = g_dinv[i];
    float4 bv = reinterpret_cast<const float4*>(bias)[k];
    acc.x = fmaf(acc.x, di, bv.x);
    acc.y = fmaf(acc.y, di, bv.y);
    acc.z = fmaf(acc.z, di, bv.z);
    acc.w = fmaf(acc.w, di, bv.w);

    if (use_bn) {
        int k4 = k << 2;
        #pragma unroll
        for (int j = 0; j < 4; j++) {
            float a = gam[k4 + j] * rsqrtf(var[k4 + j] + EPS);
            float c = bet[k4 + j] - mu[k4 + j] * a;
            float* f = (&acc.x) + j;
            *f = fmaxf(fmaf(*f, a, c), 0.0f);
        }
    }

    reinterpret_cast<float4*>(out)[(size_t)i * 16 + k] = acc;
}

// ------------------- launch (forked-graph orchestration) -------------------
extern "C" void kernel_launch(void* const* d_in, const int* in_sizes, int n_in,
                              void* d_out, int out_size)
{
    const float* x   = (const float*)d_in[0];
    const int*   ei  = (const int*)  d_in[1];
    const float* W1  = (const float*)d_in[2];
    const float* b1  = (const float*)d_in[3];
    const float* g1  = (const float*)d_in[4];
    const float* be1 = (const float*)d_in[5];
    const float* m1  = (const float*)d_in[6];
    const float* v1  = (const float*)d_in[7];
    const float* W2  = (const float*)d_in[8];
    const float* b2  = (const float*)d_in[9];
    const float* g2  = (const float*)d_in[10];
    const float* be2 = (const float*)d_in[11];
    const float* m2  = (const float*)d_in[12];
    const float* v2  = (const float*)d_in[13];
    const float* W3  = (const float*)d_in[14];
    const float* b3  = (const float*)d_in[15];

    int N = in_sizes[0] / 64;
    int E = in_sizes[1] / 2;

    const int* row = ei;
    const int* col = ei + E;

    float* out  = (float*)d_out;
    float* emb  = out;                      // global_embeddings [N,64]
    float* pred = out + (size_t)N * 64;     // hc_predictions    [N,64]

    __half* p_h   = nullptr;
    float*  p_agg = nullptr;
    cudaGetSymbolAddress((void**)&p_h,   g_h);
    cudaGetSymbolAddress((void**)&p_agg, g_agg);

    static cudaStream_t sA = nullptr, sB = nullptr;
    static cudaEvent_t evScan = nullptr, evA = nullptr, evB = nullptr;
    if (sA == nullptr) {
        cudaStreamCreateWithFlags(&sA, cudaStreamNonBlocking);
        cudaStreamCreateWithFlags(&sB, cudaStreamNonBlocking);
        cudaEventCreateWithFlags(&evScan, cudaEventDisableTiming);
        cudaEventCreateWithFlags(&evA,    cudaEventDisableTiming);
        cudaEventCreateWithFlags(&evB,    cudaEventDisableTiming);
    }

    const int T = 256;
    int gN   = (N + T - 1) / T;
    int gE4  = (E + 4 * T - 1) / (4 * T);
    int gN16 = (N * 16 + T - 1) / T;
    int gG   = (N + GEMM_ROWS - 1) / GEMM_ROWS;
    int nb   = (N + SCAN_BLK - 1) / SCAN_BLK;

    // main chain: count(+rank) -> scan -> build (no atomics)
    k_count  <<<gE4, T>>>(row, E);
    k_scan_lb<<<nb, SCAN_BLK>>>(N);
    cudaEventRecord(evScan, 0);
    k_build  <<<gE4, T>>>(row, col, E);

    // branch A (after scan): pad CSR padding slots (disjoint from build),
    // then zero deg/state for the NEXT launch
    cudaStreamWaitEvent(sA, evScan, 0);
    k_pad      <<<gN, T, 0, sA>>>(N);
    k_zero_next<<<gN, T, 0, sA>>>(N);
    cudaEventRecord(evA, sA);

    // branch B (after scan): layer-1 GEMM (needs only dinv), overlaps with build
    cudaStreamWaitEvent(sB, evScan, 0);
    k_gemm<<<gG, T, 0, sB>>>(x, W1, p_h, N);
    cudaEventRecord(evB, sB);

    // join
    cudaStreamWaitEvent(0, evA, 0);
    cudaStreamWaitEvent(0, evB, 0);

    // ---- layer 1: h = relu(bn1(agg(h) + b1)) ----
    k_pull<<<gN16, T>>>(p_h, b1, p_agg, N, g1, be1, m1, v1, 1);

    // ---- layer 2: emb = relu(bn2(conv(h, W2) + b2)) -> d_out[0:N*64] ----
    k_gemm<<<gG,   T>>>(p_agg, W2, p_h, N);
    k_pull<<<gN16, T>>>(p_h, b2, emb, N, g2, be2, m2, v2, 1);

    // ---- layer 3: pred = conv(emb, W3) + b3 -> d_out[N*64:] ----
    k_gemm<<<gG,   T>>>(emb, W3, p_h, N);
    k_pull<<<gN16, T>>>(p_h, b3, pred, N, nullptr, nullptr, nullptr, nullptr, 0);
}

// round 11
// speedup vs baseline: 1.3618x; 1.0379x over previous
#include <cuda_runtime.h>
#include <cuda_fp16.h>
#include <math.h>

#define NMAX 100000
#define EMAX 1600000
#define CSRMAX (EMAX + 8 * NMAX)     // padded CSR capacity (pad to multiple of 8)
#define EPS 1e-5f
#define SCAN_BLK 1024
#define MAX_BLKS 128                 // ceil(100000/1024)=98 <= 128

// ---- device scratch (no allocations allowed). All zero at module load. ----
__device__ int      g_deg [NMAX];        // re-zeroed by k_pad_zero each launch
__device__ int      g_off [NMAX + 1];
__device__ unsigned g_state[MAX_BLKS];   // re-zeroed by k_pad_zero each launch
__device__ float    g_dinv[NMAX];
__device__ int      g_rank[EMAX];        // within-row rank of each edge
__device__ int      g_csr [CSRMAX];      // real slots by k_build, padding by k_pad_zero
__device__ __half   g_h   [(size_t)(NMAX + 1) * 64];  // gemm outputs; row NMAX never written => 0
__device__ __half   g_hb  [(size_t)(NMAX + 1) * 64];  // pull outputs; row NMAX never written => 0

// ---------- count + rank: one atomic pass; rank[e] = old degree ----------
__global__ void k_count(const int* __restrict__ row, int E) {
    int t = blockIdx.x * blockDim.x + threadIdx.x;
    int stride = gridDim.x * blockDim.x;
    #pragma unroll
    for (int j = 0; j < 4; j++) {
        int e = t + j * stride;
        if (e < E) g_rank[e] = atomicAdd(&g_deg[row[e]], 1);
    }
}

// ---------- decoupled-lookback scan (warp-parallel lookback) + dinv ----------
__global__ __launch_bounds__(SCAN_BLK)
void k_scan_lb(int N) {
    __shared__ int warp_sums[32];
    __shared__ int s_prefix;

    int bid  = blockIdx.x;
    int tid  = threadIdx.x;
    int lane = tid & 31;
    int wid  = tid >> 5;
    int i    = bid * SCAN_BLK + tid;

    int v = (i < N) ? g_deg[i] : 0;
    if (i < N) g_dinv[i] = rsqrtf((float)v + 1.0f);   // +1 = self loop
    int vp = (v + 7) & ~7;                            // pad degree to multiple of 8

    int x = vp;
    #pragma unroll
    for (int d = 1; d < 32; d <<= 1) {
        int t = __shfl_up_sync(0xFFFFFFFFu, x, d);
        if (lane >= d) x += t;
    }
    if (lane == 31) warp_sums[wid] = x;
    __syncthreads();
    if (wid == 0) {
        int y = warp_sums[lane];
        #pragma unroll
        for (int d = 1; d < 32; d <<= 1) {
            int t = __shfl_up_sync(0xFFFFFFFFu, y, d);
            if (lane >= d) y += t;
        }
        warp_sums[lane] = y;
    }
    __syncthreads();

    int block_incl  = x + (wid > 0 ? warp_sums[wid - 1] : 0);
    int block_total = warp_sums[31];

    if (wid == 0) {
        if (bid == 0) {
            if (lane == 0) {
                s_prefix = 0;
                atomicExch(&g_state[0], (2u << 28) | (unsigned)block_total);
            }
        } else {
            if (lane == 0)
                atomicExch(&g_state[bid], (1u << 28) | (unsigned)block_total);
            int run = 0;
            int j0 = bid - 1;
            while (true) {
                int idx = j0 - lane;
                unsigned st = (idx >= 0) ? atomicAdd(&g_state[idx], 0u) : (2u << 28);
                if (__any_sync(0xFFFFFFFFu, (st >> 28) == 0u)) { __nanosleep(20); continue; }
                unsigned pm = __ballot_sync(0xFFFFFFFFu, (st >> 28) == 2u);
                if (pm) {
                    int L = __ffs((int)pm) - 1;
                    int val = (lane <= L) ? (int)(st & 0x0FFFFFFFu) : 0;
                    run += __reduce_add_sync(0xFFFFFFFFu, val);
                    break;
                } else {
                    run += __reduce_add_sync(0xFFFFFFFFu, (int)(st & 0x0FFFFFFFu));
                    j0 -= 32;
                }
            }
            if (lane == 0) {
                s_prefix = run;
                atomicExch(&g_state[bid], (2u << 28) | (unsigned)(run + block_total));
            }
        }
    }
    __syncthreads();

    if (tid == 0 && bid == (int)gridDim.x - 1)
        g_off[N] = s_prefix + block_total;

    int ex = s_prefix + block_incl - vp;              // exclusive prefix (8-aligned)
    if (i < N) g_off[i] = ex;
}

// ---------- pad padding slots + zero deg/state for the NEXT launch ----------
__global__ void k_pad_zero(int N) {
    int i = blockIdx.x * blockDim.x + threadIdx.x;
    if (i < MAX_BLKS) g_state[i] = 0;
    if (i >= N) return;
    int d = g_deg[i];
    int p = g_off[i] + d;
    int e = g_off[i] + ((d + 7) & ~7);
    for (; p < e; p++) g_csr[p] = NMAX;
    g_deg[i] = 0;
}

// ---------- scatter real edges: NO atomics (rank precomputed) ----------
__global__ void k_build(const int* __restrict__ row, const int* __restrict__ col, int E) {
    int t = blockIdx.x * blockDim.x + threadIdx.x;
    int stride = gridDim.x * blockDim.x;
    #pragma unroll
    for (int j = 0; j < 4; j++) {
        int e = t + j * stride;
        if (e < E) {
            int pos = g_off[row[e]] + g_rank[e];
            g_csr[pos] = col[e];
        }
    }
}

// ---------- scale: h[i,:] *= dinv[i] (fp32 math, fp16 storage) ----------
__global__ void k_scale(__half* __restrict__ h, int N) {
    int idx = blockIdx.x * blockDim.x + threadIdx.x;
    if (idx >= N * 16) return;
    int i = idx >> 4;
    float di = g_dinv[i];
    uint2* h2 = reinterpret_cast<uint2*>(h);
    uint2 v = h2[idx];
    float2 f0 = __half22float2(*reinterpret_cast<__half2*>(&v.x));
    float2 f1 = __half22float2(*reinterpret_cast<__half2*>(&v.y));
    __half2 r0 = __floats2half2_rn(f0.x * di, f0.y * di);
    __half2 r1 = __floats2half2_rn(f1.x * di, f1.y * di);
    uint2 st;
    st.x = *reinterpret_cast<unsigned*>(&r0);
    st.y = *reinterpret_cast<unsigned*>(&r1);
    h2[idx] = st;
}

// ------------------- GEMM (fp32 input, NO dinv scale): for layer 1 early start ----------
#define GEMM_ROWS 64

__global__ __launch_bounds__(256)
void k_gemm_f32(const float* __restrict__ in, const float* __restrict__ W,
                __half* __restrict__ out, int N)
{
    __shared__ float Wt[64][66];
    __shared__ float Xs[GEMM_ROWS][64];

    int tid = threadIdx.x;
    int row0 = blockIdx.x * GEMM_ROWS;

    #pragma unroll
    for (int i = tid; i < 64 * 64; i += 256) {
        int k = i >> 6, c = i & 63;
        Wt[c][k] = W[i];
    }
    #pragma unroll
    for (int i = tid; i < GEMM_ROWS * 16; i += 256) {
        int r = i >> 4, k4 = (i & 15);
        int gr = row0 + r;
        float4 v = (gr < N) ? reinterpret_cast<const float4*>(in)[(size_t)gr * 16 + k4]
                            : make_float4(0.f, 0.f, 0.f, 0.f);
        reinterpret_cast<float4*>(&Xs[r][0])[k4] = v;
    }
    __syncthreads();

    int cg = tid & 15;
    int rg = tid >> 4;
    int r0 = rg * 4;

    unsigned long long acc[4][4];
    #pragma unroll
    for (int a = 0; a < 4; a++)
        #pragma unroll
        for (int b = 0; b < 4; b++)
            acc[a][b] = 0ULL;

    #pragma unroll 8
    for (int kp = 0; kp < 32; kp++) {
        unsigned long long xv[4], wv[4];
        #pragma unroll
        for (int a = 0; a < 4; a++)
            xv[a] = *reinterpret_cast<const unsigned long long*>(&Xs[r0 + a][kp * 2]);
        #pragma unroll
        for (int b = 0; b < 4; b++)
            wv[b] = *reinterpret_cast<const unsigned long long*>(&Wt[cg + 16 * b][kp * 2]);
        #pragma unroll
        for (int a = 0; a < 4; a++)
            #pragma unroll
            for (int b = 0; b < 4; b++)
                asm("fma.rn.f32x2 %0, %1, %2, %0;"
                    : "+l"(acc[a][b]) : "l"(xv[a]), "l"(wv[b]));
    }

    #pragma unroll
    for (int a = 0; a < 4; a++) {
        int gr = row0 + r0 + a;
        if (gr < N) {
            #pragma unroll
            for (int b = 0; b < 4; b++) {
                float lo, hi;
                asm("mov.b64 {%0,%1}, %2;" : "=f"(lo), "=f"(hi) : "l"(acc[a][b]));
                out[(size_t)gr * 64 + cg + 16 * b] = __float2half_rn(lo + hi);
            }
        }
    }
}

// ------------------- GEMM (fp16 input, dinv-scaled fp16 output): layers 2-3 ----------
__global__ __launch_bounds__(256)
void k_gemm_f16(const __half* __restrict__ in, const float* __restrict__ W,
                __half* __restrict__ out, int N)
{
    __shared__ float Wt[64][66];
    __shared__ float Xs[GEMM_ROWS][64];

    int tid = threadIdx.x;
    int row0 = blockIdx.x * GEMM_ROWS;

    #pragma unroll
    for (int i = tid; i < 64 * 64; i += 256) {
        int k = i >> 6, c = i & 63;
        Wt[c][k] = W[i];
    }
    #pragma unroll
    for (int i = tid; i < GEMM_ROWS * 16; i += 256) {
        int r = i >> 4, k4 = (i & 15);
        int gr = row0 + r;
        uint2 v = (gr < N) ? reinterpret_cast<const uint2*>(in)[(size_t)gr * 16 + k4]
                           : make_uint2(0u, 0u);
        float2 f0 = __half22float2(*reinterpret_cast<__half2*>(&v.x));
        float2 f1 = __half22float2(*reinterpret_cast<__half2*>(&v.y));
        reinterpret_cast<float4*>(&Xs[r][0])[k4] = make_float4(f0.x, f0.y, f1.x, f1.y);
    }
    __syncthreads();

    int cg = tid & 15;
    int rg = tid >> 4;
    int r0 = rg * 4;

    unsigned long long acc[4][4];
    #pragma unroll
    for (int a = 0; a < 4; a++)
        #pragma unroll
        for (int b = 0; b < 4; b++)
            acc[a][b] = 0ULL;

    #pragma unroll 8
    for (int kp = 0; kp < 32; kp++) {
        unsigned long long xv[4], wv[4];
        #pragma unroll
        for (int a = 0; a < 4; a++)
            xv[a] = *reinterpret_cast<const unsigned long long*>(&Xs[r0 + a][kp * 2]);
        #pragma unroll
        for (int b = 0; b < 4; b++)
            wv[b] = *reinterpret_cast<const unsigned long long*>(&Wt[cg + 16 * b][kp * 2]);
        #pragma unroll
        for (int a = 0; a < 4; a++)
            #pragma unroll
            for (int b = 0; b < 4; b++)
                asm("fma.rn.f32x2 %0, %1, %2, %0;"
                    : "+l"(acc[a][b]) : "l"(xv[a]), "l"(wv[b]));
    }

    #pragma unroll
    for (int a = 0; a < 4; a++) {
        int gr = row0 + r0 + a;
        if (gr < N) {
            float di = g_dinv[gr];
            #pragma unroll
            for (int b = 0; b < 4; b++) {
                float lo, hi;
                asm("mov.b64 {%0,%1}, %2;" : "=f"(lo), "=f"(hi) : "l"(acc[a][b]));
                out[(size_t)gr * 64 + cg + 16 * b] = __float2half_rn((lo + hi) * di);
            }
        }
    }
}

// ------------------- pull aggregation (fp16 gathers, fp32 accumulate) ----------
// 16-chunk fast path + exact 8-tail (offsets padded to multiple of 8).
__global__ __launch_bounds__(256)
void k_pull(const __half* __restrict__ h, const float* __restrict__ bias,
            __half* __restrict__ out16, float* __restrict__ out32, int N,
            const float* __restrict__ gam, const float* __restrict__ bet,
            const float* __restrict__ mu,  const float* __restrict__ var,
            int use_bn)
{
    int idx = blockIdx.x * blockDim.x + threadIdx.x;
    if (idx >= N * 16) return;
    int i = idx >> 4, k = idx & 15;

    const uint2* h2 = reinterpret_cast<const uint2*>(h);

    float4 acc;
    {   // self term
        uint2 sv = __ldg(&h2[(size_t)i * 16 + k]);
        float2 f0 = __half22float2(*reinterpret_cast<__half2*>(&sv.x));
        float2 f1 = __half22float2(*reinterpret_cast<__half2*>(&sv.y));
        acc.x = f0.x; acc.y = f0.y; acc.z = f1.x; acc.w = f1.y;
    }

    int p   = g_off[i];
    int end = g_off[i + 1];

    while (p + 16 <= end) {
        const int4* c4 = reinterpret_cast<const int4*>(&g_csr[p]);
        int4 a0 = __ldg(c4 + 0);
        int4 a1 = __ldg(c4 + 1);
        int4 a2 = __ldg(c4 + 2);
        int4 a3 = __ldg(c4 + 3);
        int cj[16] = { a0.x, a0.y, a0.z, a0.w,
                       a1.x, a1.y, a1.z, a1.w,
                       a2.x, a2.y, a2.z, a2.w,
                       a3.x, a3.y, a3.z, a3.w };
        #pragma unroll
        for (int jp = 0; jp < 8; jp++) {
            uint2 v0 = __ldg(&h2[(size_t)cj[2 * jp]     * 16 + k]);
            uint2 v1 = __ldg(&h2[(size_t)cj[2 * jp + 1] * 16 + k]);
            __half2 s0 = __hadd2(*reinterpret_cast<__half2*>(&v0.x),
                                 *reinterpret_cast<__half2*>(&v1.x));
            __half2 s1 = __hadd2(*reinterpret_cast<__half2*>(&v0.y),
                                 *reinterpret_cast<__half2*>(&v1.y));
            float2 f0 = __half22float2(s0);
            float2 f1 = __half22float2(s1);
            acc.x += f0.x; acc.y += f0.y; acc.z += f1.x; acc.w += f1.y;
        }
        p += 16;
    }
    if (p < end) {   // exactly 8 left (padding guarantees)
        const int4* c4 = reinterpret_cast<const int4*>(&g_csr[p]);
        int4 a0 = __ldg(c4 + 0);
        int4 a1 = __ldg(c4 + 1);
        int cj[8] = { a0.x, a0.y, a0.z, a0.w, a1.x, a1.y, a1.z, a1.w };
        #pragma unroll
        for (int jp = 0; jp < 4; jp++) {
            uint2 v0 = __ldg(&h2[(size_t)cj[2 * jp]     * 16 + k]);
            uint2 v1 = __ldg(&h2[(size_t)cj[2 * jp + 1] * 16 + k]);
            __half2 s0 = __hadd2(*reinterpret_cast<__half2*>(&v0.x),
                                 *reinterpret_cast<__half2*>(&v1.x));
            __half2 s1 = __hadd2(*reinterpret_cast<__half2*>(&v0.y),
                                 *reinterpret_cast<__half2*>(&v1.y));
            float2 f0 = __half22float2(s0);
            float2 f1 = __half22float2(s1);
            acc.x += f0.x; acc.y += f0.y; acc.z += f1.x; acc.w += f1.y;
        }
    }

    float di = g_dinv[i];
    float4 bv = reinterpret_cast<const float4*>(bias)[k];
    acc.x = fmaf(acc.x, di, bv.x);
    acc.y = fmaf(acc.y, di, bv.y);
    acc.z = fmaf(acc.z, di, bv.z);
    acc.w = fmaf(acc.w, di, bv.w);

    if (use_bn) {
        int k4 = k << 2;
        #pragma unroll
        for (int j = 0; j < 4; j++) {
            float a = gam[k4 + j] * rsqrtf(var[k4 + j] + EPS);
            float c = bet[k4 + j] - mu[k4 + j] * a;
            float* f = (&acc.x) + j;
            *f = fmaxf(fmaf(*f, a, c), 0.0f);
        }
    }

    if (out16) {
        __half2 r0 = __floats2half2_rn(acc.x, acc.y);
        __half2 r1 = __floats2half2_rn(acc.z, acc.w);
        uint2 st;
        st.x = *reinterpret_cast<unsigned*>(&r0);
        st.y = *reinterpret_cast<unsigned*>(&r1);
        reinterpret_cast<uint2*>(out16)[(size_t)i * 16 + k] = st;
    }
    if (out32)
        reinterpret_cast<float4*>(out32)[(size_t)i * 16 + k] = acc;
}

// ------------------- launch (forked-graph orchestration) -------------------
extern "C" void kernel_launch(void* const* d_in, const int* in_sizes, int n_in,
                              void* d_out, int out_size)
{
    const float* x   = (const float*)d_in[0];
    const int*   ei  = (const int*)  d_in[1];
    const float* W1  = (const float*)d_in[2];
    const float* b1  = (const float*)d_in[3];
    const float* g1  = (const float*)d_in[4];
    const float* be1 = (const float*)d_in[5];
    const float* m1  = (const float*)d_in[6];
    const float* v1  = (const float*)d_in[7];
    const float* W2  = (const float*)d_in[8];
    const float* b2  = (const float*)d_in[9];
    const float* g2  = (const float*)d_in[10];
    const float* be2 = (const float*)d_in[11];
    const float* m2  = (const float*)d_in[12];
    const float* v2  = (const float*)d_in[13];
    const float* W3  = (const float*)d_in[14];
    const float* b3  = (const float*)d_in[15];

    int N = in_sizes[0] / 64;
    int E = in_sizes[1] / 2;

    const int* row = ei;
    const int* col = ei + E;

    float* out  = (float*)d_out;
    float* emb  = out;                      // global_embeddings [N,64]
    float* pred = out + (size_t)N * 64;     // hc_predictions    [N,64]

    __half *p_h = nullptr, *p_hb = nullptr;
    cudaGetSymbolAddress((void**)&p_h,  g_h);
    cudaGetSymbolAddress((void**)&p_hb, g_hb);

    static cudaStream_t sA = nullptr, sB = nullptr;
    static cudaEvent_t evFork = nullptr, evScan = nullptr, evA = nullptr, evB = nullptr;
    if (sA == nullptr) {
        cudaStreamCreateWithFlags(&sA, cudaStreamNonBlocking);
        cudaStreamCreateWithFlags(&sB, cudaStreamNonBlocking);
        cudaEventCreateWithFlags(&evFork, cudaEventDisableTiming);
        cudaEventCreateWithFlags(&evScan, cudaEventDisableTiming);
        cudaEventCreateWithFlags(&evA,    cudaEventDisableTiming);
        cudaEventCreateWithFlags(&evB,    cudaEventDisableTiming);
    }

    const int T = 256;
    int gN   = (N + T - 1) / T;
    int gE4  = (E + 4 * T - 1) / (4 * T);
    int gN16 = (N * 16 + T - 1) / T;
    int gG   = (N + GEMM_ROWS - 1) / GEMM_ROWS;
    int nb   = (N + SCAN_BLK - 1) / SCAN_BLK;

    // fork: branch B starts gemm1 (unscaled) immediately, overlapping count
    cudaEventRecord(evFork, 0);
    cudaStreamWaitEvent(sB, evFork, 0);
    k_gemm_f32<<<gG, T, 0, sB>>>(x, W1, p_h, N);

    // main chain: count(+rank) -> scan(+dinv) -> build (no atomics)
    k_count  <<<gE4, T>>>(row, E);
    k_scan_lb<<<nb, SCAN_BLK>>>(N);
    cudaEventRecord(evScan, 0);
    k_build  <<<gE4, T>>>(row, col, E);

    // branch A (after scan): pad padding slots + zero deg/state for next launch
    cudaStreamWaitEvent(sA, evScan, 0);
    k_pad_zero<<<gN, T, 0, sA>>>(N);
    cudaEventRecord(evA, sA);

    // branch B (after scan): apply dinv to gemm1 output
    cudaStreamWaitEvent(sB, evScan, 0);
    k_scale<<<gN16, T, 0, sB>>>(p_h, N);
    cudaEventRecord(evB, sB);

    // join
    cudaStreamWaitEvent(0, evA, 0);
    cudaStreamWaitEvent(0, evB, 0);

    // ---- layer 1: hb = fp16( relu(bn1(agg(h) + b1)) ) ----
    k_pull<<<gN16, T>>>(p_h, b1, p_hb, nullptr, N, g1, be1, m1, v1, 1);

    // ---- layer 2: h = gemm(hb, W2)*dinv; emb/hb = relu(bn2(agg(h) + b2)) ----
    k_gemm_f16<<<gG, T>>>(p_hb, W2, p_h, N);
    k_pull<<<gN16, T>>>(p_h, b2, p_hb, emb, N, g2, be2, m2, v2, 1);

    // ---- layer 3: h = gemm(hb, W3)*dinv; pred = agg(h) + b3 ----
    k_gemm_f16<<<gG, T>>>(p_hb, W3, p_h, N);
    k_pull<<<gN16, T>>>(p_h, b3, nullptr, pred, N, nullptr, nullptr, nullptr, nullptr, 0);
}